// round 10
// baseline (speedup 1.0000x reference)
#include <cuda_runtime.h>
#include <cuda_bf16.h>
#include <cstdint>

// FPQuantizer: per-row absmax clip is the identity, so the reference reduces
// to a pure elementwise flex-fp8 quantizer:
//   bias = 7.15625 (exact bf16)
//   L    = max(floor(log2|x| + bias), 1)
//   s    = 2^(L-12) * 2^(-0.15625)
//   out  = rint(x / s) * s            (rint == round-half-even == jnp.round)
// Transcendental-free via exponent bit tricks:
//   floor(log2|x| + 7.15625) = e + 7 + (mant >= 2^0.84375)
//
// R10: R9 warp-contiguous structure (best bench: 81.95us), loads switched
// from .cs (evict-first) to .lu (LAST-USE, __ldlu): read lines are dead after
// first touch, so let L2 drop them immediately instead of keeping them at
// evict-first priority — maximizes L2 room for store write-coalescing.
// This is the final untested cache-policy knob; R1-R9 established a hard
// 6.2-6.36 TB/s mixed-R/W plateau across occ 51-83%, MLP 1-8, block 256/512,
// persistent vs one-shot, store .cs/.wb, block- vs warp-contiguous tiling.

#define QT_THRESH 1.79470907f   // 2^0.84375, fp32-rounded
#define QT_C      0.89735454f   // 2^(-0.15625)
#define QT_CINV   1.11438674f   // 2^(+0.15625)

__device__ __forceinline__ float fpq_quantize(float x) {
    uint32_t b = __float_as_uint(x) & 0x7fffffffu;
    int e = (int)(b >> 23) - 127;
    float mant = __uint_as_float((b & 0x7fffffu) | 0x3f800000u);
    int L = e + 7 + (mant >= QT_THRESH ? 1 : 0);
    L = (L < 1) ? 1 : L;                       // x==0 -> L clamped to 1 -> out 0. Matches ref.
    int k = L - 12;
    float p    = __uint_as_float((uint32_t)(k + 127) << 23);
    float pinv = __uint_as_float((uint32_t)(127 - k) << 23);
    return rintf(x * (pinv * QT_CINV)) * (p * QT_C);
}

__device__ __forceinline__ float4 fpq_quantize4(float4 v) {
    float4 q;
    q.x = fpq_quantize(v.x);
    q.y = fpq_quantize(v.y);
    q.z = fpq_quantize(v.z);
    q.w = fpq_quantize(v.w);
    return q;
}

#define THREADS 512
#define VPT 4   // float4 vectors per thread

// Each warp owns a contiguous run of 32*VPT float4s (2KB); its 4 loads are
// consecutive 512B lines, front-batched (MLP=4).
__global__ __launch_bounds__(THREADS) void FPQuantizer_76312978915927_kernel(
    const float4* __restrict__ x, float4* __restrict__ out, int n4)
{
    int warp = threadIdx.x >> 5;
    int lane = threadIdx.x & 31;
    int base = blockIdx.x * (THREADS * VPT) + warp * (32 * VPT) + lane;

    if (base + (VPT - 1) * 32 < n4) {
        // front-batch 4 independent last-use loads (line droppable after read)
        float4 v0 = __ldlu(x + base + 0 * 32);
        float4 v1 = __ldlu(x + base + 1 * 32);
        float4 v2 = __ldlu(x + base + 2 * 32);
        float4 v3 = __ldlu(x + base + 3 * 32);
        __stcs(out + base + 0 * 32, fpq_quantize4(v0));
        __stcs(out + base + 1 * 32, fpq_quantize4(v1));
        __stcs(out + base + 2 * 32, fpq_quantize4(v2));
        __stcs(out + base + 3 * 32, fpq_quantize4(v3));
    } else {
        // ragged tail block (not hit for 8192x8192: 16M float4s / 2048 exact)
        #pragma unroll
        for (int k = 0; k < VPT; ++k) {
            int i = base + k * 32;
            if (i < n4) __stcs(out + i, fpq_quantize4(__ldlu(x + i)));
        }
    }
}

// Scalar tail kernel (defensive; n divisible by 4 here so it won't launch)
__global__ void FPQuantizer_tail_kernel(const float* __restrict__ x,
                                        float* __restrict__ out,
                                        int start, int n)
{
    int i = start + blockIdx.x * blockDim.x + threadIdx.x;
    if (i < n) out[i] = fpq_quantize(x[i]);
}

extern "C" void kernel_launch(void* const* d_in, const int* in_sizes, int n_in,
                              void* d_out, int out_size)
{
    const float* x = (const float*)d_in[0];
    float* out = (float*)d_out;

    int n = out_size;
    int n4 = n >> 2;                        // number of float4 elements
    const int per_block = THREADS * VPT;    // float4s per block

    if (n4 > 0) {
        int blocks = (n4 + per_block - 1) / per_block;
        FPQuantizer_76312978915927_kernel<<<blocks, THREADS>>>(
            (const float4*)x, (float4*)out, n4);
    }
    int tail_start = n4 << 2;
    int tail = n - tail_start;
    if (tail > 0) {
        FPQuantizer_tail_kernel<<<1, 128>>>(x, out, tail_start, n);
    }
}

// round 11
// speedup vs baseline: 1.0043x; 1.0043x over previous
#include <cuda_runtime.h>
#include <cuda_bf16.h>
#include <cstdint>

// FPQuantizer — FINAL (R10 locked in).
//
// Algebra: the reference's per-row absmax clip is the identity
// (clip(x, -max|row|, +max|row|) == x), so the whole op is a pure elementwise
// flex-fp8 quantizer:
//   bias = bf16(2^4 - log2(448) + log2(2 - 2^-4) - 1) = 7.15625 (exact in bf16)
//   L    = max(floor(log2|x| + bias), 1)
//   s    = 2^(L-12) * 2^(-0.15625)
//   out  = rint(x / s) * s            (rint == round-half-even == jnp.round)
// Transcendental-free: floor(log2|x| + 7.15625) = e + 7 + (mant >= 2^0.84375),
// scales via exponent-field construction (exact pow2) * fp32 constants.
// This reduction is what keeps the kernel memory-bound instead of MUFU-bound.
//
// Perf characterization (R1-R10): all coalesced MLP>=4 variants pin at
// 6.21-6.37 TB/s across occupancy 51-83%, MLP 1-8, block 256/512, one-shot/
// persistent/pipelined, store .cs/.wb, load .cs/.lu, block- vs warp-contiguous
// tiling => chip-level mixed-50/50-R/W memory ceiling (path-independent
// ~6300 B/cyc LTS/DRAM cap; TMA hits the same wall). Traffic irreducible
// (256 MB fp32 read + 256 MB fp32 write, no reuse). Kernel is at roofline:
// ~75.5 us kernel = 512 MB / 6.37 TB/s; compute pipes all <= 34%.
//
// Config: warp-contiguous tiling (each warp owns one 2KB run; every
// LDG.128/STG.128 warp-coalesced 512B), 4 front-batched __ldlu loads per
// thread (MLP=4, last-use: L2 may drop read lines after first touch),
// __stcs stores, 512 threads/block, 32 regs.

#define QT_THRESH 1.79470907f   // 2^0.84375, fp32-rounded
#define QT_C      0.89735454f   // 2^(-0.15625)
#define QT_CINV   1.11438674f   // 2^(+0.15625)

__device__ __forceinline__ float fpq_quantize(float x) {
    uint32_t b = __float_as_uint(x) & 0x7fffffffu;
    int e = (int)(b >> 23) - 127;
    float mant = __uint_as_float((b & 0x7fffffu) | 0x3f800000u);
    int L = e + 7 + (mant >= QT_THRESH ? 1 : 0);
    L = (L < 1) ? 1 : L;                       // x==0 -> L clamped to 1 -> out 0. Matches ref.
    int k = L - 12;
    float p    = __uint_as_float((uint32_t)(k + 127) << 23);
    float pinv = __uint_as_float((uint32_t)(127 - k) << 23);
    return rintf(x * (pinv * QT_CINV)) * (p * QT_C);
}

__device__ __forceinline__ float4 fpq_quantize4(float4 v) {
    float4 q;
    q.x = fpq_quantize(v.x);
    q.y = fpq_quantize(v.y);
    q.z = fpq_quantize(v.z);
    q.w = fpq_quantize(v.w);
    return q;
}

#define THREADS 512
#define VPT 4   // float4 vectors per thread

// Each warp owns a contiguous run of 32*VPT float4s (2KB); its 4 loads are
// consecutive 512B lines, front-batched (MLP=4).
__global__ __launch_bounds__(THREADS) void FPQuantizer_76312978915927_kernel(
    const float4* __restrict__ x, float4* __restrict__ out, int n4)
{
    int warp = threadIdx.x >> 5;
    int lane = threadIdx.x & 31;
    int base = blockIdx.x * (THREADS * VPT) + warp * (32 * VPT) + lane;

    if (base + (VPT - 1) * 32 < n4) {
        // front-batch 4 independent last-use loads (line droppable after read)
        float4 v0 = __ldlu(x + base + 0 * 32);
        float4 v1 = __ldlu(x + base + 1 * 32);
        float4 v2 = __ldlu(x + base + 2 * 32);
        float4 v3 = __ldlu(x + base + 3 * 32);
        __stcs(out + base + 0 * 32, fpq_quantize4(v0));
        __stcs(out + base + 1 * 32, fpq_quantize4(v1));
        __stcs(out + base + 2 * 32, fpq_quantize4(v2));
        __stcs(out + base + 3 * 32, fpq_quantize4(v3));
    } else {
        // ragged tail block (not hit for 8192x8192: 16M float4s / 2048 exact)
        #pragma unroll
        for (int k = 0; k < VPT; ++k) {
            int i = base + k * 32;
            if (i < n4) __stcs(out + i, fpq_quantize4(__ldlu(x + i)));
        }
    }
}

// Scalar tail kernel (defensive; n divisible by 4 here so it won't launch)
__global__ void FPQuantizer_tail_kernel(const float* __restrict__ x,
                                        float* __restrict__ out,
                                        int start, int n)
{
    int i = start + blockIdx.x * blockDim.x + threadIdx.x;
    if (i < n) out[i] = fpq_quantize(x[i]);
}

extern "C" void kernel_launch(void* const* d_in, const int* in_sizes, int n_in,
                              void* d_out, int out_size)
{
    const float* x = (const float*)d_in[0];
    float* out = (float*)d_out;

    int n = out_size;
    int n4 = n >> 2;                        // number of float4 elements
    const int per_block = THREADS * VPT;    // float4s per block

    if (n4 > 0) {
        int blocks = (n4 + per_block - 1) / per_block;
        FPQuantizer_76312978915927_kernel<<<blocks, THREADS>>>(
            (const float4*)x, (float4*)out, n4);
    }
    int tail_start = n4 << 2;
    int tail = n - tail_start;
    if (tail > 0) {
        FPQuantizer_tail_kernel<<<1, 128>>>(x, out, tail_start, n);
    }
}